// round 1
// baseline (speedup 1.0000x reference)
#include <cuda_runtime.h>

#define BATCH 4
#define CH    256
#define CQK   32
#define NN    4096
#define TI    8

// ---------------- scratch (device globals; no allocation allowed) ----------
__device__ float g_q[(size_t)BATCH * NN * CQK];            //  2 MB  [B,N,32]
__device__ float g_k[(size_t)BATCH * NN * CQK];            //  2 MB  [B,N,32]
__device__ float g_v[(size_t)BATCH * NN * CH];             // 16 MB  [B,N,256]
__device__ float g_ao[(size_t)BATCH * NN * CH];            // 16 MB  [B,N,256]

// ---------------- packed fp32x2 helpers (FFMA2 path) -----------------------
__device__ __forceinline__ unsigned long long pack2(float a, float b) {
    unsigned long long r;
    asm("mov.b64 %0, {%1, %2};" : "=l"(r) : "f"(a), "f"(b));
    return r;
}
__device__ __forceinline__ void ffma2(unsigned long long& d,
                                      unsigned long long a,
                                      unsigned long long b) {
    asm("fma.rn.f32x2 %0, %1, %2, %0;" : "+l"(d) : "l"(a), "l"(b));
}
__device__ __forceinline__ float2 unpack2(unsigned long long v) {
    float lo, hi;
    asm("mov.b64 {%0, %1}, %2;" : "=f"(lo), "=f"(hi) : "l"(v));
    return make_float2(lo, hi);
}

// ============================================================================
// Kernel 1: q/k projection.  q[b,n,d] = bq[d] + sum_c wq[d,c] x[b,c,n]
// Block: (b, 32-wide n tile), 256 threads.  thread = (ng: 4 n's, cg: 2 d's)
// ============================================================================
__global__ void __launch_bounds__(256)
proj_qk_kernel(const float* __restrict__ x,
               const float* __restrict__ wq, const float* __restrict__ bq,
               const float* __restrict__ wk, const float* __restrict__ bk)
{
    __shared__ __align__(16) float xs[CH * 32];   // [c][n] 32 KB
    const int b   = blockIdx.y;
    const int n0  = blockIdx.x * 32;
    const int tid = threadIdx.x;

    const float* xb = x + (size_t)b * CH * NN + n0;
    for (int idx = tid; idx < CH * 32; idx += 256) {
        int c = idx >> 5, nn = idx & 31;
        xs[c * 32 + nn] = xb[(size_t)c * NN + nn];
    }
    __syncthreads();

    const int ng = tid & 7;          // n sub-tile: n = ng*4 .. +3
    const int cg = tid >> 3;         // 0..31 -> 2 outputs each (64 d total)
    const bool isq = (cg < 16);
    const float* w    = isq ? wq : wk;
    const float* bias = isq ? bq : bk;
    const int d0 = (isq ? cg : cg - 16) * 2;

    float a0[4], a1[4];
    const float b0 = bias[d0], b1 = bias[d0 + 1];
#pragma unroll
    for (int i = 0; i < 4; i++) { a0[i] = b0; a1[i] = b1; }

    const float* w0p = w + (size_t)d0 * CH;
    const float* w1p = w + (size_t)(d0 + 1) * CH;

    for (int c4 = 0; c4 < CH; c4 += 4) {
        float wr0[4], wr1[4];
        *(float4*)wr0 = *(const float4*)(w0p + c4);
        *(float4*)wr1 = *(const float4*)(w1p + c4);
#pragma unroll
        for (int i = 0; i < 4; i++) {
            float xv[4];
            *(float4*)xv = *(const float4*)(xs + (c4 + i) * 32 + ng * 4);
#pragma unroll
            for (int nn = 0; nn < 4; nn++) {
                a0[nn] += wr0[i] * xv[nn];
                a1[nn] += wr1[i] * xv[nn];
            }
        }
    }

    float* outp = (isq ? g_q : g_k) + ((size_t)b * NN + n0 + ng * 4) * CQK + d0;
#pragma unroll
    for (int nn = 0; nn < 4; nn++)
        *(float2*)(outp + (size_t)nn * CQK) = make_float2(a0[nn], a1[nn]);
}

// ============================================================================
// Kernel 2: v projection.  v[b,n,c] = bv[c] + sum_c' wv[c,c'] x[b,c',n]
// thread = (ng: 4 n's, cg: 8 c's)
// ============================================================================
__global__ void __launch_bounds__(256)
proj_v_kernel(const float* __restrict__ x,
              const float* __restrict__ wv, const float* __restrict__ bv)
{
    __shared__ __align__(16) float xs[CH * 32];
    const int b   = blockIdx.y;
    const int n0  = blockIdx.x * 32;
    const int tid = threadIdx.x;

    const float* xb = x + (size_t)b * CH * NN + n0;
    for (int idx = tid; idx < CH * 32; idx += 256) {
        int c = idx >> 5, nn = idx & 31;
        xs[c * 32 + nn] = xb[(size_t)c * NN + nn];
    }
    __syncthreads();

    const int ng = tid & 7;
    const int cg = tid >> 3;          // 0..31 -> 8 channels each

    float acc[8][4];
#pragma unroll
    for (int cc = 0; cc < 8; cc++) {
        float bb = bv[cg * 8 + cc];
#pragma unroll
        for (int i = 0; i < 4; i++) acc[cc][i] = bb;
    }

    for (int c4 = 0; c4 < CH; c4 += 4) {
        float xv[4][4];
#pragma unroll
        for (int i = 0; i < 4; i++)
            *(float4*)xv[i] = *(const float4*)(xs + (c4 + i) * 32 + ng * 4);
#pragma unroll
        for (int cc = 0; cc < 8; cc++) {
            float wr[4];
            *(float4*)wr = *(const float4*)(wv + (size_t)(cg * 8 + cc) * CH + c4);
#pragma unroll
            for (int i = 0; i < 4; i++) {
                acc[cc][0] += wr[i] * xv[i][0];
                acc[cc][1] += wr[i] * xv[i][1];
                acc[cc][2] += wr[i] * xv[i][2];
                acc[cc][3] += wr[i] * xv[i][3];
            }
        }
    }

    float* vout = g_v + ((size_t)b * NN + n0 + ng * 4) * CH + cg * 8;
#pragma unroll
    for (int nn = 0; nn < 4; nn++) {
        *(float4*)(vout + (size_t)nn * CH) =
            make_float4(acc[0][nn], acc[1][nn], acc[2][nn], acc[3][nn]);
        *(float4*)(vout + (size_t)nn * CH + 4) =
            make_float4(acc[4][nn], acc[5][nn], acc[6][nn], acc[7][nn]);
    }
}

// ============================================================================
// Kernel 3: fused attention for TI query rows per block.
// Phase 1: s_ij = q_i . k_j  for all j (P row kept in SMEM), running max
// Phase e: p = exp(s - m), sum
// Phase 2: out[c] = (1/Z) sum_j p_j v[j,c]   (FFMA2 hot loop)
// ============================================================================
__global__ void __launch_bounds__(256)
attn_kernel()
{
    extern __shared__ __align__(16) float sm[];
    float* p   = sm;                   // TI*NN
    float* qs  = sm + TI * NN;         // TI*32
    float* red = qs + TI * 32;         // 8*TI
    float* gm  = red + 8 * TI;         // TI
    float* gsc = gm + TI;              // TI

    const int b    = blockIdx.y;
    const int i0   = blockIdx.x * TI;
    const int tid  = threadIdx.x;
    const int lane = tid & 31;
    const int warp = tid >> 5;

    qs[tid] = g_q[((size_t)b * NN + i0 + (tid >> 5)) * CQK + (tid & 31)];
    __syncthreads();

    // ---------------- phase 1: scores + local max ----------------
    float mloc[TI];
#pragma unroll
    for (int t = 0; t < TI; t++) mloc[t] = -1e30f;

    const float4* kb = (const float4*)(g_k + (size_t)b * NN * CQK);
    for (int j = tid; j < NN; j += 256) {
        float4 kr[8];
#pragma unroll
        for (int t = 0; t < 8; t++) kr[t] = kb[j * 8 + t];
#pragma unroll
        for (int ti = 0; ti < TI; ti++) {
            const float4* q4 = (const float4*)(qs + ti * 32);
            float s = 0.f;
#pragma unroll
            for (int t = 0; t < 8; t++) {
                float4 qv = q4[t];
                s += qv.x * kr[t].x + qv.y * kr[t].y
                   + qv.z * kr[t].z + qv.w * kr[t].w;
            }
            p[ti * NN + j] = s;
            mloc[ti] = fmaxf(mloc[ti], s);
        }
    }

#pragma unroll
    for (int ti = 0; ti < TI; ti++)
#pragma unroll
        for (int o = 16; o; o >>= 1)
            mloc[ti] = fmaxf(mloc[ti], __shfl_xor_sync(0xffffffffu, mloc[ti], o));
    if (lane == 0)
#pragma unroll
        for (int ti = 0; ti < TI; ti++) red[warp * TI + ti] = mloc[ti];
    __syncthreads();
    if (tid < TI) {
        float m = red[tid];
#pragma unroll
        for (int w = 1; w < 8; w++) m = fmaxf(m, red[w * TI + tid]);
        gm[tid] = m;
    }
    __syncthreads();

    float gmr[TI];
#pragma unroll
    for (int ti = 0; ti < TI; ti++) gmr[ti] = gm[ti];

    // ---------------- phase e: exp + sum ----------------
    float sloc[TI];
#pragma unroll
    for (int ti = 0; ti < TI; ti++) sloc[ti] = 0.f;
    for (int j = tid; j < NN; j += 256) {
#pragma unroll
        for (int ti = 0; ti < TI; ti++) {
            float e = __expf(p[ti * NN + j] - gmr[ti]);
            p[ti * NN + j] = e;
            sloc[ti] += e;
        }
    }
#pragma unroll
    for (int ti = 0; ti < TI; ti++)
#pragma unroll
        for (int o = 16; o; o >>= 1)
            sloc[ti] += __shfl_xor_sync(0xffffffffu, sloc[ti], o);
    if (lane == 0)
#pragma unroll
        for (int ti = 0; ti < TI; ti++) red[warp * TI + ti] = sloc[ti];
    __syncthreads();
    if (tid < TI) {
        float s = 0.f;
#pragma unroll
        for (int w = 0; w < 8; w++) s += red[w * TI + tid];
        gsc[tid] = 1.0f / s;
    }
    __syncthreads();

    // ---------------- phase 2: out = P @ V  (FFMA2) ----------------
    const int cq = tid & 63;     // channel quad: channels cq*4 .. +3
    const int jj = tid >> 6;     // 0..3 : j-stripe

    const float4* vb = (const float4*)(g_v + (size_t)b * NN * CH);
    unsigned long long acc[TI][2];
#pragma unroll
    for (int ti = 0; ti < TI; ti++) { acc[ti][0] = 0ull; acc[ti][1] = 0ull; }

#pragma unroll 4
    for (int j = jj; j < NN; j += 4) {
        float4 vv = vb[(size_t)j * 64 + cq];
        unsigned long long v01 = pack2(vv.x, vv.y);
        unsigned long long v23 = pack2(vv.z, vv.w);
#pragma unroll
        for (int ti = 0; ti < TI; ti++) {
            float pv = p[ti * NN + j];
            unsigned long long p2 = pack2(pv, pv);
            ffma2(acc[ti][0], p2, v01);
            ffma2(acc[ti][1], p2, v23);
        }
    }
    __syncthreads();                       // done reading p; reuse as scratch

    float* part = p;                        // 4 * TI * CH floats
#pragma unroll
    for (int ti = 0; ti < TI; ti++) {
        float2 x01 = unpack2(acc[ti][0]);
        float2 x23 = unpack2(acc[ti][1]);
        ((float4*)part)[(jj * TI + ti) * 64 + cq] =
            make_float4(x01.x, x01.y, x23.x, x23.y);
    }
    __syncthreads();

    float* aob = g_ao + ((size_t)b * NN + i0) * CH;
#pragma unroll
    for (int ti = 0; ti < TI; ti++) {
        float s = part[(0 * TI + ti) * CH + tid]
                + part[(1 * TI + ti) * CH + tid]
                + part[(2 * TI + ti) * CH + tid]
                + part[(3 * TI + ti) * CH + tid];
        aob[(size_t)ti * CH + tid] = s * gsc[ti];
    }
}

// ============================================================================
// Kernel 4: output projection + residual.
// y[b,c,n] = x[b,c,n] + bg[c] + sum_c' wg[c,c'] ao[b,n,c']
// ============================================================================
__global__ void __launch_bounds__(256)
final_kernel(const float* __restrict__ x,
             const float* __restrict__ wg, const float* __restrict__ bg,
             float* __restrict__ y)
{
    __shared__ __align__(16) float as[CH * 36];   // [c'][n] padded, 36 KB
    const int b   = blockIdx.y;
    const int n0  = blockIdx.x * 32;
    const int tid = threadIdx.x;

    const float* aob = g_ao + ((size_t)b * NN + n0) * CH;
    for (int idx = tid; idx < 32 * CH; idx += 256) {
        int nn = idx >> 8, c = idx & 255;
        as[c * 36 + nn] = aob[(size_t)nn * CH + c];
    }
    __syncthreads();

    const int ng = tid & 7;
    const int cg = tid >> 3;

    float acc[8][4];
#pragma unroll
    for (int cc = 0; cc < 8; cc++) {
        float bb = bg[cg * 8 + cc];
#pragma unroll
        for (int i = 0; i < 4; i++) acc[cc][i] = bb;
    }

    for (int c4 = 0; c4 < CH; c4 += 4) {
        float xv[4][4];
#pragma unroll
        for (int i = 0; i < 4; i++)
            *(float4*)xv[i] = *(const float4*)(as + (c4 + i) * 36 + ng * 4);
#pragma unroll
        for (int cc = 0; cc < 8; cc++) {
            float wr[4];
            *(float4*)wr = *(const float4*)(wg + (size_t)(cg * 8 + cc) * CH + c4);
#pragma unroll
            for (int i = 0; i < 4; i++) {
                acc[cc][0] += wr[i] * xv[i][0];
                acc[cc][1] += wr[i] * xv[i][1];
                acc[cc][2] += wr[i] * xv[i][2];
                acc[cc][3] += wr[i] * xv[i][3];
            }
        }
    }

    const float* xb = x + (size_t)b * CH * NN + n0 + ng * 4;
    float*       yb = y + (size_t)b * CH * NN + n0 + ng * 4;
#pragma unroll
    for (int cc = 0; cc < 8; cc++) {
        int c = cg * 8 + cc;
        float4 xr = *(const float4*)(xb + (size_t)c * NN);
        *(float4*)(yb + (size_t)c * NN) =
            make_float4(xr.x + acc[cc][0], xr.y + acc[cc][1],
                        xr.z + acc[cc][2], xr.w + acc[cc][3]);
    }
}

// ============================================================================
extern "C" void kernel_launch(void* const* d_in, const int* in_sizes, int n_in,
                              void* d_out, int out_size)
{
    const float* x  = (const float*)d_in[0];
    const float* wq = (const float*)d_in[1];
    const float* bq = (const float*)d_in[2];
    const float* wk = (const float*)d_in[3];
    const float* bk = (const float*)d_in[4];
    const float* wv = (const float*)d_in[5];
    const float* bv = (const float*)d_in[6];
    const float* wg = (const float*)d_in[7];
    const float* bg = (const float*)d_in[8];
    float* y = (float*)d_out;

    const size_t attn_smem =
        (size_t)(TI * NN + TI * 32 + 8 * TI + TI + TI) * sizeof(float);
    cudaFuncSetAttribute(attn_kernel,
                         cudaFuncAttributeMaxDynamicSharedMemorySize,
                         (int)attn_smem);

    proj_qk_kernel<<<dim3(NN / 32, BATCH), 256>>>(x, wq, bq, wk, bk);
    proj_v_kernel <<<dim3(NN / 32, BATCH), 256>>>(x, wv, bv);
    attn_kernel   <<<dim3(NN / TI, BATCH), 256, attn_smem>>>();
    final_kernel  <<<dim3(NN / 32, BATCH), 256>>>(x, wg, bg, y);
}

// round 2
// speedup vs baseline: 1.5879x; 1.5879x over previous
#include <cuda_runtime.h>

#define BATCH 4
#define CH    256
#define CQK   32
#define NN    4096

// attention tiling
#define TQ     64
#define TJ     128
#define NTILES (NN / TJ)

// smem float offsets for attn kernel
#define QS_OFF 0                          // [32][64]
#define KS_OFF 2048                       // [32][132]
#define ES_OFF (2048 + 32*132)            // 6272   [128][68]
#define VS_OFF (6272 + 128*68)            // 14976  [128][264]
#define SMEM_FLOATS (14976 + 128*264)     // 48768 floats = 195072 B

// ---------------- scratch (device globals; no allocation allowed) ----------
__device__ float g_q[(size_t)BATCH * NN * CQK];            //  2 MB  [B,N,32]
__device__ float g_k[(size_t)BATCH * NN * CQK];            //  2 MB  [B,N,32]
__device__ float g_v[(size_t)BATCH * NN * CH];             // 16 MB  [B,N,256]
__device__ float g_ao[(size_t)BATCH * NN * CH];            // 16 MB  [B,N,256]

// ---------------- packed fp32x2 helpers (FFMA2 path) -----------------------
__device__ __forceinline__ unsigned long long pack2(float a, float b) {
    unsigned long long r;
    asm("mov.b64 %0, {%1, %2};" : "=l"(r) : "f"(a), "f"(b));
    return r;
}
__device__ __forceinline__ void ffma2(unsigned long long& d,
                                      unsigned long long a,
                                      unsigned long long b) {
    asm("fma.rn.f32x2 %0, %1, %2, %0;" : "+l"(d) : "l"(a), "l"(b));
}
__device__ __forceinline__ float2 unpack2(unsigned long long v) {
    float lo, hi;
    asm("mov.b64 {%0, %1}, %2;" : "=f"(lo), "=f"(hi) : "l"(v));
    return make_float2(lo, hi);
}

// ============================================================================
// Kernel 1: q/k projection.  q[b,n,d] = bq[d] + sum_c wq[d,c] x[b,c,n]
// ============================================================================
__global__ void __launch_bounds__(256)
proj_qk_kernel(const float* __restrict__ x,
               const float* __restrict__ wq, const float* __restrict__ bq,
               const float* __restrict__ wk, const float* __restrict__ bk)
{
    __shared__ __align__(16) float xs[CH * 32];   // [c][n] 32 KB
    const int b   = blockIdx.y;
    const int n0  = blockIdx.x * 32;
    const int tid = threadIdx.x;

    const float* xb = x + (size_t)b * CH * NN + n0;
    for (int idx = tid; idx < CH * 32; idx += 256) {
        int c = idx >> 5, nn = idx & 31;
        xs[c * 32 + nn] = xb[(size_t)c * NN + nn];
    }
    __syncthreads();

    const int ng = tid & 7;          // n sub-tile: n = ng*4 .. +3
    const int cg = tid >> 3;         // 0..31 -> 2 outputs each (64 d total)
    const bool isq = (cg < 16);
    const float* w    = isq ? wq : wk;
    const float* bias = isq ? bq : bk;
    const int d0 = (isq ? cg : cg - 16) * 2;

    float a0[4], a1[4];
    const float b0 = bias[d0], b1 = bias[d0 + 1];
#pragma unroll
    for (int i = 0; i < 4; i++) { a0[i] = b0; a1[i] = b1; }

    const float* w0p = w + (size_t)d0 * CH;
    const float* w1p = w + (size_t)(d0 + 1) * CH;

    for (int c4 = 0; c4 < CH; c4 += 4) {
        float wr0[4], wr1[4];
        *(float4*)wr0 = *(const float4*)(w0p + c4);
        *(float4*)wr1 = *(const float4*)(w1p + c4);
#pragma unroll
        for (int i = 0; i < 4; i++) {
            float xv[4];
            *(float4*)xv = *(const float4*)(xs + (c4 + i) * 32 + ng * 4);
#pragma unroll
            for (int nn = 0; nn < 4; nn++) {
                a0[nn] += wr0[i] * xv[nn];
                a1[nn] += wr1[i] * xv[nn];
            }
        }
    }

    float* outp = (isq ? g_q : g_k) + ((size_t)b * NN + n0 + ng * 4) * CQK + d0;
#pragma unroll
    for (int nn = 0; nn < 4; nn++)
        *(float2*)(outp + (size_t)nn * CQK) = make_float2(a0[nn], a1[nn]);
}

// ============================================================================
// Kernel 2: v projection.  v[b,n,c] = bv[c] + sum_c' wv[c,c'] x[b,c',n]
// ============================================================================
__global__ void __launch_bounds__(256)
proj_v_kernel(const float* __restrict__ x,
              const float* __restrict__ wv, const float* __restrict__ bv)
{
    __shared__ __align__(16) float xs[CH * 32];
    const int b   = blockIdx.y;
    const int n0  = blockIdx.x * 32;
    const int tid = threadIdx.x;

    const float* xb = x + (size_t)b * CH * NN + n0;
    for (int idx = tid; idx < CH * 32; idx += 256) {
        int c = idx >> 5, nn = idx & 31;
        xs[c * 32 + nn] = xb[(size_t)c * NN + nn];
    }
    __syncthreads();

    const int ng = tid & 7;
    const int cg = tid >> 3;          // 0..31 -> 8 channels each

    float acc[8][4];
#pragma unroll
    for (int cc = 0; cc < 8; cc++) {
        float bb = bv[cg * 8 + cc];
#pragma unroll
        for (int i = 0; i < 4; i++) acc[cc][i] = bb;
    }

    for (int c4 = 0; c4 < CH; c4 += 4) {
        float xv[4][4];
#pragma unroll
        for (int i = 0; i < 4; i++)
            *(float4*)xv[i] = *(const float4*)(xs + (c4 + i) * 32 + ng * 4);
#pragma unroll
        for (int cc = 0; cc < 8; cc++) {
            float wr[4];
            *(float4*)wr = *(const float4*)(wv + (size_t)(cg * 8 + cc) * CH + c4);
#pragma unroll
            for (int i = 0; i < 4; i++) {
                acc[cc][0] += wr[i] * xv[i][0];
                acc[cc][1] += wr[i] * xv[i][1];
                acc[cc][2] += wr[i] * xv[i][2];
                acc[cc][3] += wr[i] * xv[i][3];
            }
        }
    }

    float* vout = g_v + ((size_t)b * NN + n0 + ng * 4) * CH + cg * 8;
#pragma unroll
    for (int nn = 0; nn < 4; nn++) {
        *(float4*)(vout + (size_t)nn * CH) =
            make_float4(acc[0][nn], acc[1][nn], acc[2][nn], acc[3][nn]);
        *(float4*)(vout + (size_t)nn * CH + 4) =
            make_float4(acc[4][nn], acc[5][nn], acc[6][nn], acc[7][nn]);
    }
}

// ============================================================================
// Kernel 3: fused single-pass attention (no max subtraction; fp32-safe here).
//   CTA: 64 queries. Loop over 32 j-tiles of 128:
//     stage K,V tiles -> S=QK^T (FFMA2) -> exp -> E smem + rowsum -> O += E.V
//   End: O /= rowsum, write g_ao.
// ============================================================================
__global__ void __launch_bounds__(256, 1)
attn_kernel()
{
    extern __shared__ __align__(16) float sm[];
    float* qs = sm + QS_OFF;   // [d][q]  row 64
    float* ks = sm + KS_OFF;   // [d][j]  row 132
    float* es = sm + ES_OFF;   // [j][q]  row 68
    float* vs = sm + VS_OFF;   // [j][c]  row 264, half-offset 132

    const int b    = blockIdx.y;
    const int i0   = blockIdx.x * TQ;
    const int tid  = threadIdx.x;
    const int w    = tid >> 5;        // warp id == q-block (8 rows)
    const int lane = tid & 31;

    // ---- stage Q tile [d][q] (once) ----
    {
        int q  = tid >> 2;
        int d0 = (tid & 3) * 8;
        const float* src = g_q + ((size_t)b * NN + i0 + q) * CQK + d0;
        float4 a = *(const float4*)src;
        float4 c = *(const float4*)(src + 4);
        qs[(d0 + 0) * TQ + q] = a.x;  qs[(d0 + 1) * TQ + q] = a.y;
        qs[(d0 + 2) * TQ + q] = a.z;  qs[(d0 + 3) * TQ + q] = a.w;
        qs[(d0 + 4) * TQ + q] = c.x;  qs[(d0 + 5) * TQ + q] = c.y;
        qs[(d0 + 6) * TQ + q] = c.z;  qs[(d0 + 7) * TQ + q] = c.w;
    }

    // persistent accumulators: 8 q rows x 8 channels (as 4 f32x2) per thread
    unsigned long long acc[8][4];
#pragma unroll
    for (int q = 0; q < 8; q++)
#pragma unroll
        for (int cpair = 0; cpair < 4; cpair++) acc[q][cpair] = 0ull;

    float rs[8];
#pragma unroll
    for (int q = 0; q < 8; q++) rs[q] = 0.f;

    const int co = (lane << 3) + ((lane >= 16) ? 4 : 0);  // vs read offset

    for (int t = 0; t < NTILES; ++t) {
        const int j0 = t * TJ;

        // ---- stage K tile: ks[d][j], transpose from g_k[b][j][d] ----
        {
            int r = tid >> 1, h = (tid & 1) * 16;
            const float* src = g_k + ((size_t)b * NN + j0 + r) * CQK + h;
#pragma unroll
            for (int i = 0; i < 4; i++) {
                float4 kk = *(const float4*)(src + i * 4);
                ks[(h + i * 4 + 0) * 132 + r] = kk.x;
                ks[(h + i * 4 + 1) * 132 + r] = kk.y;
                ks[(h + i * 4 + 2) * 132 + r] = kk.z;
                ks[(h + i * 4 + 3) * 132 + r] = kk.w;
            }
        }
        // ---- stage V tile: vs[j][c] (row 264, half-offset 132) ----
        {
            int r = tid >> 1, h = tid & 1;
            const float* src = g_v + ((size_t)b * NN + j0 + r) * CH + h * 128;
            float* dst = vs + r * 264 + h * 132;
#pragma unroll
            for (int i = 0; i < 32; i++)
                *(float4*)(dst + i * 4) = *(const float4*)(src + i * 4);
        }
        __syncthreads();

        // ---- S = Q . K^T : thread = (warp q-block) x (4 j's at lane*4) ----
        unsigned long long sacc[4][4];   // [qpair][j]
#pragma unroll
        for (int qp = 0; qp < 4; qp++)
#pragma unroll
            for (int jj = 0; jj < 4; jj++) sacc[qp][jj] = 0ull;

        {
            const float* ksp = ks + (lane << 2);
            const float* qsp = qs + (w << 3);
#pragma unroll 4
            for (int d = 0; d < CQK; d++) {
                float4 kv = *(const float4*)(ksp + d * 132);
                float4 q0 = *(const float4*)(qsp + d * TQ);
                float4 q1 = *(const float4*)(qsp + d * TQ + 4);
                unsigned long long qp0 = pack2(q0.x, q0.y);
                unsigned long long qp1 = pack2(q0.z, q0.w);
                unsigned long long qp2 = pack2(q1.x, q1.y);
                unsigned long long qp3 = pack2(q1.z, q1.w);
                unsigned long long kd0 = pack2(kv.x, kv.x);
                unsigned long long kd1 = pack2(kv.y, kv.y);
                unsigned long long kd2 = pack2(kv.z, kv.z);
                unsigned long long kd3 = pack2(kv.w, kv.w);
                ffma2(sacc[0][0], qp0, kd0); ffma2(sacc[0][1], qp0, kd1);
                ffma2(sacc[0][2], qp0, kd2); ffma2(sacc[0][3], qp0, kd3);
                ffma2(sacc[1][0], qp1, kd0); ffma2(sacc[1][1], qp1, kd1);
                ffma2(sacc[1][2], qp1, kd2); ffma2(sacc[1][3], qp1, kd3);
                ffma2(sacc[2][0], qp2, kd0); ffma2(sacc[2][1], qp2, kd1);
                ffma2(sacc[2][2], qp2, kd2); ffma2(sacc[2][3], qp2, kd3);
                ffma2(sacc[3][0], qp3, kd0); ffma2(sacc[3][1], qp3, kd1);
                ffma2(sacc[3][2], qp3, kd2); ffma2(sacc[3][3], qp3, kd3);
            }
        }

        // ---- exp (no max-sub), store E[j][q], accumulate rowsums ----
        {
            float psum[8];
#pragma unroll
            for (int q = 0; q < 8; q++) psum[q] = 0.f;

#pragma unroll
            for (int jj = 0; jj < 4; jj++) {
                float e[8];
#pragma unroll
                for (int qp = 0; qp < 4; qp++) {
                    float2 s = unpack2(sacc[qp][jj]);
                    e[qp * 2 + 0] = __expf(s.x);
                    e[qp * 2 + 1] = __expf(s.y);
                }
                int j = (lane << 2) + jj;
                *(float4*)(es + j * 68 + (w << 3)) =
                    make_float4(e[0], e[1], e[2], e[3]);
                *(float4*)(es + j * 68 + (w << 3) + 4) =
                    make_float4(e[4], e[5], e[6], e[7]);
#pragma unroll
                for (int q = 0; q < 8; q++) psum[q] += e[q];
            }
#pragma unroll
            for (int q = 0; q < 8; q++) {
#pragma unroll
                for (int o = 16; o; o >>= 1)
                    psum[q] += __shfl_xor_sync(0xffffffffu, psum[q], o);
                rs[q] += psum[q];
            }
        }
        __syncthreads();

        // ---- O += E . V  (FFMA2 hot loop) ----
        {
            const float* esp = es + (w << 3);
            const float* vsp = vs + co;
#pragma unroll 2
            for (int j = 0; j < TJ; j++) {
                float4 e0 = *(const float4*)(esp + j * 68);
                float4 e1 = *(const float4*)(esp + j * 68 + 4);
                float4 v0 = *(const float4*)(vsp + j * 264);
                float4 v1 = *(const float4*)(vsp + j * 264 + 4);
                unsigned long long vp0 = pack2(v0.x, v0.y);
                unsigned long long vp1 = pack2(v0.z, v0.w);
                unsigned long long vp2 = pack2(v1.x, v1.y);
                unsigned long long vp3 = pack2(v1.z, v1.w);
                unsigned long long ed;
                ed = pack2(e0.x, e0.x);
                ffma2(acc[0][0], ed, vp0); ffma2(acc[0][1], ed, vp1);
                ffma2(acc[0][2], ed, vp2); ffma2(acc[0][3], ed, vp3);
                ed = pack2(e0.y, e0.y);
                ffma2(acc[1][0], ed, vp0); ffma2(acc[1][1], ed, vp1);
                ffma2(acc[1][2], ed, vp2); ffma2(acc[1][3], ed, vp3);
                ed = pack2(e0.z, e0.z);
                ffma2(acc[2][0], ed, vp0); ffma2(acc[2][1], ed, vp1);
                ffma2(acc[2][2], ed, vp2); ffma2(acc[2][3], ed, vp3);
                ed = pack2(e0.w, e0.w);
                ffma2(acc[3][0], ed, vp0); ffma2(acc[3][1], ed, vp1);
                ffma2(acc[3][2], ed, vp2); ffma2(acc[3][3], ed, vp3);
                ed = pack2(e1.x, e1.x);
                ffma2(acc[4][0], ed, vp0); ffma2(acc[4][1], ed, vp1);
                ffma2(acc[4][2], ed, vp2); ffma2(acc[4][3], ed, vp3);
                ed = pack2(e1.y, e1.y);
                ffma2(acc[5][0], ed, vp0); ffma2(acc[5][1], ed, vp1);
                ffma2(acc[5][2], ed, vp2); ffma2(acc[5][3], ed, vp3);
                ed = pack2(e1.z, e1.z);
                ffma2(acc[6][0], ed, vp0); ffma2(acc[6][1], ed, vp1);
                ffma2(acc[6][2], ed, vp2); ffma2(acc[6][3], ed, vp3);
                ed = pack2(e1.w, e1.w);
                ffma2(acc[7][0], ed, vp0); ffma2(acc[7][1], ed, vp1);
                ffma2(acc[7][2], ed, vp2); ffma2(acc[7][3], ed, vp3);
            }
        }
        __syncthreads();
    }

    // ---- normalize and write out: g_ao[b][i0 + w*8 + q][lane*8 .. +8] ----
#pragma unroll
    for (int q = 0; q < 8; q++) {
        float inv = 1.0f / rs[q];
        float2 a0 = unpack2(acc[q][0]);
        float2 a1 = unpack2(acc[q][1]);
        float2 a2 = unpack2(acc[q][2]);
        float2 a3 = unpack2(acc[q][3]);
        float* dst = g_ao + ((size_t)b * NN + i0 + (w << 3) + q) * CH + (lane << 3);
        *(float4*)(dst)     = make_float4(a0.x * inv, a0.y * inv, a1.x * inv, a1.y * inv);
        *(float4*)(dst + 4) = make_float4(a2.x * inv, a2.y * inv, a3.x * inv, a3.y * inv);
    }
}

// ============================================================================
// Kernel 4: output projection + residual.
// ============================================================================
__global__ void __launch_bounds__(256)
final_kernel(const float* __restrict__ x,
             const float* __restrict__ wg, const float* __restrict__ bg,
             float* __restrict__ y)
{
    __shared__ __align__(16) float as[CH * 36];   // [c'][n] padded, 36 KB
    const int b   = blockIdx.y;
    const int n0  = blockIdx.x * 32;
    const int tid = threadIdx.x;

    const float* aob = g_ao + ((size_t)b * NN + n0) * CH;
    for (int idx = tid; idx < 32 * CH; idx += 256) {
        int nn = idx >> 8, c = idx & 255;
        as[c * 36 + nn] = aob[(size_t)nn * CH + c];
    }
    __syncthreads();

    const int ng = tid & 7;
    const int cg = tid >> 3;

    float acc[8][4];
#pragma unroll
    for (int cc = 0; cc < 8; cc++) {
        float bb = bg[cg * 8 + cc];
#pragma unroll
        for (int i = 0; i < 4; i++) acc[cc][i] = bb;
    }

    for (int c4 = 0; c4 < CH; c4 += 4) {
        float xv[4][4];
#pragma unroll
        for (int i = 0; i < 4; i++)
            *(float4*)xv[i] = *(const float4*)(as + (c4 + i) * 36 + ng * 4);
#pragma unroll
        for (int cc = 0; cc < 8; cc++) {
            float wr[4];
            *(float4*)wr = *(const float4*)(wg + (size_t)(cg * 8 + cc) * CH + c4);
#pragma unroll
            for (int i = 0; i < 4; i++) {
                acc[cc][0] += wr[i] * xv[i][0];
                acc[cc][1] += wr[i] * xv[i][1];
                acc[cc][2] += wr[i] * xv[i][2];
                acc[cc][3] += wr[i] * xv[i][3];
            }
        }
    }

    const float* xb = x + (size_t)b * CH * NN + n0 + ng * 4;
    float*       yb = y + (size_t)b * CH * NN + n0 + ng * 4;
#pragma unroll
    for (int cc = 0; cc < 8; cc++) {
        int c = cg * 8 + cc;
        float4 xr = *(const float4*)(xb + (size_t)c * NN);
        *(float4*)(yb + (size_t)c * NN) =
            make_float4(xr.x + acc[cc][0], xr.y + acc[cc][1],
                        xr.z + acc[cc][2], xr.w + acc[cc][3]);
    }
}

// ============================================================================
extern "C" void kernel_launch(void* const* d_in, const int* in_sizes, int n_in,
                              void* d_out, int out_size)
{
    const float* x  = (const float*)d_in[0];
    const float* wq = (const float*)d_in[1];
    const float* bq = (const float*)d_in[2];
    const float* wk = (const float*)d_in[3];
    const float* bk = (const float*)d_in[4];
    const float* wv = (const float*)d_in[5];
    const float* bv = (const float*)d_in[6];
    const float* wg = (const float*)d_in[7];
    const float* bg = (const float*)d_in[8];
    float* y = (float*)d_out;

    const size_t attn_smem = (size_t)SMEM_FLOATS * sizeof(float);
    cudaFuncSetAttribute(attn_kernel,
                         cudaFuncAttributeMaxDynamicSharedMemorySize,
                         (int)attn_smem);

    proj_qk_kernel<<<dim3(NN / 32, BATCH), 256>>>(x, wq, bq, wk, bk);
    proj_v_kernel <<<dim3(NN / 32, BATCH), 256>>>(x, wv, bv);
    attn_kernel   <<<dim3(NN / TQ, BATCH), 256, attn_smem>>>();
    final_kernel  <<<dim3(NN / 32, BATCH), 256>>>(x, wg, bg, y);
}

// round 5
// speedup vs baseline: 3.2911x; 2.0726x over previous
#include <cuda_runtime.h>
#include <cuda_bf16.h>
#include <cstdint>

#define BATCH 4
#define CH    256
#define CQK   32
#define NN    4096

#define TQ     128
#define TJ     128
#define NTILES (NN / TJ)   // 32

// smem layout (bf16 elements)
#define KPAD 40
#define VPAD 136
#define SM_KH 0
#define SM_KL (128 * KPAD)
#define SM_VH (2 * 128 * KPAD)
#define SM_VL (SM_VH + 256 * VPAD)
#define SM_BF16_TOTAL (SM_VL + 256 * VPAD)   // 79872 bf16 = 159744 B

// ---------------- scratch (device globals; no allocation allowed) ----------
__device__ __nv_bfloat16 g_qh[(size_t)BATCH * NN * CQK];
__device__ __nv_bfloat16 g_ql[(size_t)BATCH * NN * CQK];
__device__ __nv_bfloat16 g_kh[(size_t)BATCH * NN * CQK];
__device__ __nv_bfloat16 g_kl[(size_t)BATCH * NN * CQK];
__device__ __nv_bfloat16 g_vth[(size_t)BATCH * CH * NN];   // V^T hi [b][c][n]
__device__ __nv_bfloat16 g_vtl[(size_t)BATCH * CH * NN];   // V^T lo
__device__ float         g_ao [(size_t)BATCH * NN * CH];   // attn out [b][n][c]

// ---------------- helpers ---------------------------------------------------
__device__ __forceinline__ unsigned cvt_bf16x2(float hi, float lo) {
    unsigned r;
    asm("cvt.rn.bf16x2.f32 %0, %1, %2;" : "=r"(r) : "f"(hi), "f"(lo));
    return r;
}
__device__ __forceinline__ float f_lo(unsigned u) { return __uint_as_float(u << 16); }
__device__ __forceinline__ float f_hi(unsigned u) { return __uint_as_float(u & 0xffff0000u); }

// D += A(16x16 bf16, row) * B(16x8 bf16, col)
__device__ __forceinline__ void mma_bf16(float* d, const unsigned* a,
                                         unsigned b0, unsigned b1) {
    asm volatile(
        "mma.sync.aligned.m16n8k16.row.col.f32.bf16.bf16.f32 "
        "{%0,%1,%2,%3}, {%4,%5,%6,%7}, {%8,%9}, {%0,%1,%2,%3};"
        : "+f"(d[0]), "+f"(d[1]), "+f"(d[2]), "+f"(d[3])
        : "r"(a[0]), "r"(a[1]), "r"(a[2]), "r"(a[3]), "r"(b0), "r"(b1));
}

// ============================================================================
// Kernel 1: q/k projection -> bf16 hi/lo
// ============================================================================
__global__ void __launch_bounds__(256)
proj_qk_kernel(const float* __restrict__ x,
               const float* __restrict__ wq, const float* __restrict__ bq,
               const float* __restrict__ wk, const float* __restrict__ bk)
{
    __shared__ __align__(16) float xs[CH * 32];
    const int b   = blockIdx.y;
    const int n0  = blockIdx.x * 32;
    const int tid = threadIdx.x;

    const float* xb = x + (size_t)b * CH * NN + n0;
    for (int idx = tid; idx < CH * 32; idx += 256) {
        int c = idx >> 5, nn = idx & 31;
        xs[c * 32 + nn] = xb[(size_t)c * NN + nn];
    }
    __syncthreads();

    const int ng = tid & 7;
    const int cg = tid >> 3;
    const bool isq = (cg < 16);
    const float* w    = isq ? wq : wk;
    const float* bias = isq ? bq : bk;
    const int d0 = (isq ? cg : cg - 16) * 2;

    float a0[4], a1[4];
    const float b0 = bias[d0], b1 = bias[d0 + 1];
#pragma unroll
    for (int i = 0; i < 4; i++) { a0[i] = b0; a1[i] = b1; }

    const float* w0p = w + (size_t)d0 * CH;
    const float* w1p = w + (size_t)(d0 + 1) * CH;

    for (int c4 = 0; c4 < CH; c4 += 4) {
        float wr0[4], wr1[4];
        *(float4*)wr0 = *(const float4*)(w0p + c4);
        *(float4*)wr1 = *(const float4*)(w1p + c4);
#pragma unroll
        for (int i = 0; i < 4; i++) {
            float xv[4];
            *(float4*)xv = *(const float4*)(xs + (c4 + i) * 32 + ng * 4);
#pragma unroll
            for (int nn = 0; nn < 4; nn++) {
                a0[nn] += wr0[i] * xv[nn];
                a1[nn] += wr1[i] * xv[nn];
            }
        }
    }

    __nv_bfloat16* hq = isq ? g_qh : g_kh;
    __nv_bfloat16* lq = isq ? g_ql : g_kl;
#pragma unroll
    for (int nn = 0; nn < 4; nn++) {
        size_t base = ((size_t)b * NN + n0 + ng * 4 + nn) * CQK + d0;
        unsigned h = cvt_bf16x2(a1[nn], a0[nn]);
        unsigned l = cvt_bf16x2(a1[nn] - f_hi(h), a0[nn] - f_lo(h));
        *(unsigned*)(hq + base) = h;
        *(unsigned*)(lq + base) = l;
    }
}

// ============================================================================
// Kernel 2: v projection -> V^T bf16 hi/lo  [b][c][n]
// ============================================================================
__global__ void __launch_bounds__(256)
proj_v_kernel(const float* __restrict__ x,
              const float* __restrict__ wv, const float* __restrict__ bv)
{
    __shared__ __align__(16) float xs[CH * 32];
    const int b   = blockIdx.y;
    const int n0  = blockIdx.x * 32;
    const int tid = threadIdx.x;

    const float* xb = x + (size_t)b * CH * NN + n0;
    for (int idx = tid; idx < CH * 32; idx += 256) {
        int c = idx >> 5, nn = idx & 31;
        xs[c * 32 + nn] = xb[(size_t)c * NN + nn];
    }
    __syncthreads();

    const int ng = tid & 7;
    const int cg = tid >> 3;

    float acc[8][4];
#pragma unroll
    for (int cc = 0; cc < 8; cc++) {
        float bb = bv[cg * 8 + cc];
#pragma unroll
        for (int i = 0; i < 4; i++) acc[cc][i] = bb;
    }

    for (int c4 = 0; c4 < CH; c4 += 4) {
        float xv[4][4];
#pragma unroll
        for (int i = 0; i < 4; i++)
            *(float4*)xv[i] = *(const float4*)(xs + (c4 + i) * 32 + ng * 4);
#pragma unroll
        for (int cc = 0; cc < 8; cc++) {
            float wr[4];
            *(float4*)wr = *(const float4*)(wv + (size_t)(cg * 8 + cc) * CH + c4);
#pragma unroll
            for (int i = 0; i < 4; i++) {
                acc[cc][0] += wr[i] * xv[i][0];
                acc[cc][1] += wr[i] * xv[i][1];
                acc[cc][2] += wr[i] * xv[i][2];
                acc[cc][3] += wr[i] * xv[i][3];
            }
        }
    }

#pragma unroll
    for (int cc = 0; cc < 8; cc++) {
        int c = cg * 8 + cc;
        size_t base = ((size_t)b * CH + c) * NN + n0 + ng * 4;
        unsigned h0 = cvt_bf16x2(acc[cc][1], acc[cc][0]);
        unsigned h1 = cvt_bf16x2(acc[cc][3], acc[cc][2]);
        unsigned l0 = cvt_bf16x2(acc[cc][1] - f_hi(h0), acc[cc][0] - f_lo(h0));
        unsigned l1 = cvt_bf16x2(acc[cc][3] - f_hi(h1), acc[cc][2] - f_lo(h1));
        *(uint2*)(g_vth + base) = make_uint2(h0, h1);
        *(uint2*)(g_vtl + base) = make_uint2(l0, l1);
    }
}

// ============================================================================
// Kernel 3: HMMA flash attention. CTA = 128 q x full 4096 j, 8 warps.
// Warp owns 16 q rows; O lives in 128 fp32 regs/thread across all tiles.
// ============================================================================
__global__ void __launch_bounds__(256, 1)
attn_kernel()
{
    extern __shared__ __align__(16) __nv_bfloat16 smem[];
    __nv_bfloat16* ksh_h = smem + SM_KH;   // [128][40]
    __nv_bfloat16* ksh_l = smem + SM_KL;
    __nv_bfloat16* vsh_h = smem + SM_VH;   // [256][136] (V^T: [c][j])
    __nv_bfloat16* vsh_l = smem + SM_VL;

    const int tid  = threadIdx.x;
    const int w    = tid >> 5;
    const int lane = tid & 31;
    const int g    = lane >> 2;       // row group 0..7
    const int t    = lane & 3;        // col group 0..3
    const int b    = blockIdx.y;
    const int q0   = blockIdx.x * TQ;
    const int row0 = q0 + w * 16 + g;

    // ---- Q A-fragments (persist; loaded straight from gmem) ----
    unsigned qh[2][4], ql[2][4];
    {
        const __nv_bfloat16* qhp = g_qh + (size_t)b * NN * CQK;
        const __nv_bfloat16* qlp = g_ql + (size_t)b * NN * CQK;
#pragma unroll
        for (int kq = 0; kq < 2; kq++) {
            int c0 = kq * 16 + t * 2;
            qh[kq][0] = *(const unsigned*)(qhp + (size_t)row0 * CQK + c0);
            qh[kq][1] = *(const unsigned*)(qhp + (size_t)(row0 + 8) * CQK + c0);
            qh[kq][2] = *(const unsigned*)(qhp + (size_t)row0 * CQK + c0 + 8);
            qh[kq][3] = *(const unsigned*)(qhp + (size_t)(row0 + 8) * CQK + c0 + 8);
            ql[kq][0] = *(const unsigned*)(qlp + (size_t)row0 * CQK + c0);
            ql[kq][1] = *(const unsigned*)(qlp + (size_t)(row0 + 8) * CQK + c0);
            ql[kq][2] = *(const unsigned*)(qlp + (size_t)row0 * CQK + c0 + 8);
            ql[kq][3] = *(const unsigned*)(qlp + (size_t)(row0 + 8) * CQK + c0 + 8);
        }
    }

    // persistent O accumulators: 32 c-blocks x 4 fp32
    float o[32][4];
#pragma unroll
    for (int cb = 0; cb < 32; cb++) {
        o[cb][0] = 0.f; o[cb][1] = 0.f; o[cb][2] = 0.f; o[cb][3] = 0.f;
    }
    float rs0 = 0.f, rs1 = 0.f;

    for (int tl = 0; tl < NTILES; tl++) {
        const int j0 = tl * TJ;

        // ---- stage K tile [j][d] hi/lo, pad 40 (16 elems = 2x uint4 each) ----
        {
            int r = tid >> 1, h = tid & 1;
            size_t src = ((size_t)b * NN + j0 + r) * CQK + h * 16;
            *(uint4*)(ksh_h + r * KPAD + h * 16)     = *(const uint4*)(g_kh + src);
            *(uint4*)(ksh_h + r * KPAD + h * 16 + 8) = *(const uint4*)(g_kh + src + 8);
            *(uint4*)(ksh_l + r * KPAD + h * 16)     = *(const uint4*)(g_kl + src);
            *(uint4*)(ksh_l + r * KPAD + h * 16 + 8) = *(const uint4*)(g_kl + src + 8);
        }
        // ---- stage V^T tile [c][j] hi/lo, pad 136 ----
        {
            size_t src = ((size_t)b * CH + tid) * NN + j0;
            __nv_bfloat16* dh = vsh_h + tid * VPAD;
            __nv_bfloat16* dl = vsh_l + tid * VPAD;
#pragma unroll
            for (int i = 0; i < 16; i++) {
                *(uint4*)(dh + i * 8) = *(const uint4*)(g_vth + src + i * 8);
                *(uint4*)(dl + i * 8) = *(const uint4*)(g_vtl + src + i * 8);
            }
        }
        __syncthreads();

        for (int kb = 0; kb < 8; kb++) {
            // ---- QK: two j-subblocks of 8 -> S fragments ----
            float s0[4] = {0.f, 0.f, 0.f, 0.f};
            float s1[4] = {0.f, 0.f, 0.f, 0.f};
#pragma unroll
            for (int jbi = 0; jbi < 2; jbi++) {
                int jb = kb * 2 + jbi;
                const __nv_bfloat16* krh = ksh_h + (jb * 8 + g) * KPAD;
                const __nv_bfloat16* krl = ksh_l + (jb * 8 + g) * KPAD;
                float* sd = jbi ? s1 : s0;
#pragma unroll
                for (int kq = 0; kq < 2; kq++) {
                    int c0 = kq * 16 + t * 2;
                    unsigned kh0 = *(const unsigned*)(krh + c0);
                    unsigned kh1 = *(const unsigned*)(krh + c0 + 8);
                    unsigned kl0 = *(const unsigned*)(krl + c0);
                    unsigned kl1 = *(const unsigned*)(krl + c0 + 8);
                    mma_bf16(sd, qh[kq], kh0, kh1);
                    mma_bf16(sd, qh[kq], kl0, kl1);
                    mma_bf16(sd, ql[kq], kh0, kh1);
                }
            }

            // ---- exp (no max-sub; fp32-safe: |s| <= ~40) ----
            float e00 = __expf(s0[0]), e01 = __expf(s0[1]);
            float e02 = __expf(s0[2]), e03 = __expf(s0[3]);
            float e10 = __expf(s1[0]), e11 = __expf(s1[1]);
            float e12 = __expf(s1[2]), e13 = __expf(s1[3]);
            rs0 += e00 + e01 + e10 + e11;
            rs1 += e02 + e03 + e12 + e13;

            // D-frag -> A-frag repack (exact layout match), hi/lo split
            unsigned pa[4], pl[4];
            pa[0] = cvt_bf16x2(e01, e00);
            pa[1] = cvt_bf16x2(e03, e02);
            pa[2] = cvt_bf16x2(e11, e10);
            pa[3] = cvt_bf16x2(e13, e12);
            pl[0] = cvt_bf16x2(e01 - f_hi(pa[0]), e00 - f_lo(pa[0]));
            pl[1] = cvt_bf16x2(e03 - f_hi(pa[1]), e02 - f_lo(pa[1]));
            pl[2] = cvt_bf16x2(e11 - f_hi(pa[2]), e10 - f_lo(pa[2]));
            pl[3] = cvt_bf16x2(e13 - f_hi(pa[3]), e12 - f_lo(pa[3]));

            // ---- PV: O += Ph*Vh + Ph*Vl + Pl*Vh over 32 c-blocks ----
            const __nv_bfloat16* vbh = vsh_h + g * VPAD + kb * 16 + t * 2;
            const __nv_bfloat16* vbl = vsh_l + g * VPAD + kb * 16 + t * 2;
#pragma unroll
            for (int cb = 0; cb < 32; cb++) {
                unsigned vh0 = *(const unsigned*)(vbh + cb * 8 * VPAD);
                unsigned vh1 = *(const unsigned*)(vbh + cb * 8 * VPAD + 8);
                unsigned vl0 = *(const unsigned*)(vbl + cb * 8 * VPAD);
                unsigned vl1 = *(const unsigned*)(vbl + cb * 8 * VPAD + 8);
                mma_bf16(o[cb], pa, vh0, vh1);
                mma_bf16(o[cb], pa, vl0, vl1);
                mma_bf16(o[cb], pl, vh0, vh1);
            }
        }
        __syncthreads();
    }

    // ---- rowsum reduce across the 4 lanes sharing a row ----
    rs0 += __shfl_xor_sync(0xffffffffu, rs0, 1);
    rs0 += __shfl_xor_sync(0xffffffffu, rs0, 2);
    rs1 += __shfl_xor_sync(0xffffffffu, rs1, 1);
    rs1 += __shfl_xor_sync(0xffffffffu, rs1, 2);
    const float inv0 = 1.0f / rs0;
    const float inv1 = 1.0f / rs1;

    float* d0p = g_ao + ((size_t)b * NN + row0) * CH;
    float* d1p = g_ao + ((size_t)b * NN + row0 + 8) * CH;
#pragma unroll
    for (int cb = 0; cb < 32; cb++) {
        *(float2*)(d0p + cb * 8 + t * 2) = make_float2(o[cb][0] * inv0, o[cb][1] * inv0);
        *(float2*)(d1p + cb * 8 + t * 2) = make_float2(o[cb][2] * inv1, o[cb][3] * inv1);
    }
}

// ============================================================================
// Kernel 4: output projection + residual.
// ============================================================================
__global__ void __launch_bounds__(256)
final_kernel(const float* __restrict__ x,
             const float* __restrict__ wg, const float* __restrict__ bg,
             float* __restrict__ y)
{
    __shared__ __align__(16) float as[CH * 36];
    const int b   = blockIdx.y;
    const int n0  = blockIdx.x * 32;
    const int tid = threadIdx.x;

    const float* aob = g_ao + ((size_t)b * NN + n0) * CH;
    for (int idx = tid; idx < 32 * CH; idx += 256) {
        int nn = idx >> 8, c = idx & 255;
        as[c * 36 + nn] = aob[(size_t)nn * CH + c];
    }
    __syncthreads();

    const int ng = tid & 7;
    const int cg = tid >> 3;

    float acc[8][4];
#pragma unroll
    for (int cc = 0; cc < 8; cc++) {
        float bb = bg[cg * 8 + cc];
#pragma unroll
        for (int i = 0; i < 4; i++) acc[cc][i] = bb;
    }

    for (int c4 = 0; c4 < CH; c4 += 4) {
        float xv[4][4];
#pragma unroll
        for (int i = 0; i < 4; i++)
            *(float4*)xv[i] = *(const float4*)(as + (c4 + i) * 36 + ng * 4);
#pragma unroll
        for (int cc = 0; cc < 8; cc++) {
            float wr[4];
            *(float4*)wr = *(const float4*)(wg + (size_t)(cg * 8 + cc) * CH + c4);
#pragma unroll
            for (int i = 0; i < 4; i++) {
                acc[cc][0] += wr[i] * xv[i][0];
                acc[cc][1] += wr[i] * xv[i][1];
                acc[cc][2] += wr[i] * xv[i][2];
                acc[cc][3] += wr[i] * xv[i][3];
            }
        }
    }

    const float* xb = x + (size_t)b * CH * NN + n0 + ng * 4;
    float*       yb = y + (size_t)b * CH * NN + n0 + ng * 4;
#pragma unroll
    for (int cc = 0; cc < 8; cc++) {
        int c = cg * 8 + cc;
        float4 xr = *(const float4*)(xb + (size_t)c * NN);
        *(float4*)(yb + (size_t)c * NN) =
            make_float4(xr.x + acc[cc][0], xr.y + acc[cc][1],
                        xr.z + acc[cc][2], xr.w + acc[cc][3]);
    }
}

// ============================================================================
extern "C" void kernel_launch(void* const* d_in, const int* in_sizes, int n_in,
                              void* d_out, int out_size)
{
    const float* x  = (const float*)d_in[0];
    const float* wq = (const float*)d_in[1];
    const float* bq = (const float*)d_in[2];
    const float* wk = (const float*)d_in[3];
    const float* bk = (const float*)d_in[4];
    const float* wv = (const float*)d_in[5];
    const float* bv = (const float*)d_in[6];
    const float* wg = (const float*)d_in[7];
    const float* bg = (const float*)d_in[8];
    float* y = (float*)d_out;

    const int attn_smem = SM_BF16_TOTAL * 2;   // bytes
    cudaFuncSetAttribute(attn_kernel,
                         cudaFuncAttributeMaxDynamicSharedMemorySize, attn_smem);

    proj_qk_kernel<<<dim3(NN / 32, BATCH), 256>>>(x, wq, bq, wk, bk);
    proj_v_kernel <<<dim3(NN / 32, BATCH), 256>>>(x, wv, bv);
    attn_kernel   <<<dim3(NN / TQ, BATCH), 256, attn_smem>>>();
    final_kernel  <<<dim3(NN / 32, BATCH), 256>>>(x, wg, bg, y);
}

// round 6
// speedup vs baseline: 3.5109x; 1.0668x over previous
#include <cuda_runtime.h>
#include <cuda_bf16.h>
#include <cstdint>

#define BATCH 4
#define CH    256
#define CQK   32
#define NN    4096

#define TQ     128
#define TJ     64
#define NTILES (NN / TJ)   // 64

// smem element (bf16) layout: two buffers, each K hi/lo + V^T hi/lo
#define KPAD 40
#define VPAD 72
#define KHe 0
#define KLe 2560                     // 64*40
#define VHe 5120
#define VLe (5120 + 256 * VPAD)      // 5120 + 18432 = 23552
#define BUFE (23552 + 256 * VPAD)    // 41984 elements per buffer
#define SM_BF16_TOTAL (2 * BUFE)     // 83968 el = 167936 B
// byte offsets for cp.async
#define KH_B 0
#define KL_B 5120
#define VH_B 10240
#define VL_B 47104
#define BUFB 83968

// ---------------- scratch (device globals; no allocation allowed) ----------
__device__ __nv_bfloat16 g_qh[(size_t)BATCH * NN * CQK];
__device__ __nv_bfloat16 g_ql[(size_t)BATCH * NN * CQK];
__device__ __nv_bfloat16 g_kh[(size_t)BATCH * NN * CQK];
__device__ __nv_bfloat16 g_kl[(size_t)BATCH * NN * CQK];
__device__ __nv_bfloat16 g_vth[(size_t)BATCH * CH * NN];   // V^T hi [b][c][n]
__device__ __nv_bfloat16 g_vtl[(size_t)BATCH * CH * NN];   // V^T lo
__device__ float         g_ao [(size_t)BATCH * NN * CH];   // attn out [b][n][c]

// ---------------- helpers ---------------------------------------------------
__device__ __forceinline__ unsigned cvt_bf16x2(float hi, float lo) {
    unsigned r;
    asm("cvt.rn.bf16x2.f32 %0, %1, %2;" : "=r"(r) : "f"(hi), "f"(lo));
    return r;
}
__device__ __forceinline__ float f_lo(unsigned u) { return __uint_as_float(u << 16); }
__device__ __forceinline__ float f_hi(unsigned u) { return __uint_as_float(u & 0xffff0000u); }

__device__ __forceinline__ uint32_t smem_u32(const void* p) {
    uint32_t a;
    asm("{ .reg .u64 t; cvta.to.shared.u64 t, %1; cvt.u32.u64 %0, t; }"
        : "=r"(a) : "l"(p));
    return a;
}
__device__ __forceinline__ void cp16(uint32_t dst, const void* src) {
    asm volatile("cp.async.cg.shared.global [%0], [%1], 16;"
                 :: "r"(dst), "l"(src) : "memory");
}
#define CP_COMMIT() asm volatile("cp.async.commit_group;" ::: "memory")
#define CP_WAIT1()  asm volatile("cp.async.wait_group 1;" ::: "memory")

// D += A(16x16 bf16, row) * B(16x8 bf16, col)
__device__ __forceinline__ void mma_bf16(float* d, const unsigned* a,
                                         unsigned b0, unsigned b1) {
    asm volatile(
        "mma.sync.aligned.m16n8k16.row.col.f32.bf16.bf16.f32 "
        "{%0,%1,%2,%3}, {%4,%5,%6,%7}, {%8,%9}, {%0,%1,%2,%3};"
        : "+f"(d[0]), "+f"(d[1]), "+f"(d[2]), "+f"(d[3])
        : "r"(a[0]), "r"(a[1]), "r"(a[2]), "r"(a[3]), "r"(b0), "r"(b1));
}

// ============================================================================
// Kernel 1: q/k projection -> bf16 hi/lo
// ============================================================================
__global__ void __launch_bounds__(256)
proj_qk_kernel(const float* __restrict__ x,
               const float* __restrict__ wq, const float* __restrict__ bq,
               const float* __restrict__ wk, const float* __restrict__ bk)
{
    __shared__ __align__(16) float xs[CH * 32];
    const int b   = blockIdx.y;
    const int n0  = blockIdx.x * 32;
    const int tid = threadIdx.x;

    const float* xb = x + (size_t)b * CH * NN + n0;
    for (int idx = tid; idx < CH * 32; idx += 256) {
        int c = idx >> 5, nn = idx & 31;
        xs[c * 32 + nn] = xb[(size_t)c * NN + nn];
    }
    __syncthreads();

    const int ng = tid & 7;
    const int cg = tid >> 3;
    const bool isq = (cg < 16);
    const float* w    = isq ? wq : wk;
    const float* bias = isq ? bq : bk;
    const int d0 = (isq ? cg : cg - 16) * 2;

    float a0[4], a1[4];
    const float b0 = bias[d0], b1 = bias[d0 + 1];
#pragma unroll
    for (int i = 0; i < 4; i++) { a0[i] = b0; a1[i] = b1; }

    const float* w0p = w + (size_t)d0 * CH;
    const float* w1p = w + (size_t)(d0 + 1) * CH;

    for (int c4 = 0; c4 < CH; c4 += 4) {
        float wr0[4], wr1[4];
        *(float4*)wr0 = *(const float4*)(w0p + c4);
        *(float4*)wr1 = *(const float4*)(w1p + c4);
#pragma unroll
        for (int i = 0; i < 4; i++) {
            float xv[4];
            *(float4*)xv = *(const float4*)(xs + (c4 + i) * 32 + ng * 4);
#pragma unroll
            for (int nn = 0; nn < 4; nn++) {
                a0[nn] += wr0[i] * xv[nn];
                a1[nn] += wr1[i] * xv[nn];
            }
        }
    }

    __nv_bfloat16* hq = isq ? g_qh : g_kh;
    __nv_bfloat16* lq = isq ? g_ql : g_kl;
#pragma unroll
    for (int nn = 0; nn < 4; nn++) {
        size_t base = ((size_t)b * NN + n0 + ng * 4 + nn) * CQK + d0;
        unsigned h = cvt_bf16x2(a1[nn], a0[nn]);
        unsigned l = cvt_bf16x2(a1[nn] - f_hi(h), a0[nn] - f_lo(h));
        *(unsigned*)(hq + base) = h;
        *(unsigned*)(lq + base) = l;
    }
}

// ============================================================================
// Kernel 2: v projection -> V^T bf16 hi/lo  [b][c][n]
// ============================================================================
__global__ void __launch_bounds__(256)
proj_v_kernel(const float* __restrict__ x,
              const float* __restrict__ wv, const float* __restrict__ bv)
{
    __shared__ __align__(16) float xs[CH * 32];
    const int b   = blockIdx.y;
    const int n0  = blockIdx.x * 32;
    const int tid = threadIdx.x;

    const float* xb = x + (size_t)b * CH * NN + n0;
    for (int idx = tid; idx < CH * 32; idx += 256) {
        int c = idx >> 5, nn = idx & 31;
        xs[c * 32 + nn] = xb[(size_t)c * NN + nn];
    }
    __syncthreads();

    const int ng = tid & 7;
    const int cg = tid >> 3;

    float acc[8][4];
#pragma unroll
    for (int cc = 0; cc < 8; cc++) {
        float bb = bv[cg * 8 + cc];
#pragma unroll
        for (int i = 0; i < 4; i++) acc[cc][i] = bb;
    }

    for (int c4 = 0; c4 < CH; c4 += 4) {
        float xv[4][4];
#pragma unroll
        for (int i = 0; i < 4; i++)
            *(float4*)xv[i] = *(const float4*)(xs + (c4 + i) * 32 + ng * 4);
#pragma unroll
        for (int cc = 0; cc < 8; cc++) {
            float wr[4];
            *(float4*)wr = *(const float4*)(wv + (size_t)(cg * 8 + cc) * CH + c4);
#pragma unroll
            for (int i = 0; i < 4; i++) {
                acc[cc][0] += wr[i] * xv[i][0];
                acc[cc][1] += wr[i] * xv[i][1];
                acc[cc][2] += wr[i] * xv[i][2];
                acc[cc][3] += wr[i] * xv[i][3];
            }
        }
    }

#pragma unroll
    for (int cc = 0; cc < 8; cc++) {
        int c = cg * 8 + cc;
        size_t base = ((size_t)b * CH + c) * NN + n0 + ng * 4;
        unsigned h0 = cvt_bf16x2(acc[cc][1], acc[cc][0]);
        unsigned h1 = cvt_bf16x2(acc[cc][3], acc[cc][2]);
        unsigned l0 = cvt_bf16x2(acc[cc][1] - f_hi(h0), acc[cc][0] - f_lo(h0));
        unsigned l1 = cvt_bf16x2(acc[cc][3] - f_hi(h1), acc[cc][2] - f_lo(h1));
        *(uint2*)(g_vth + base) = make_uint2(h0, h1);
        *(uint2*)(g_vtl + base) = make_uint2(l0, l1);
    }
}

// ============================================================================
// Kernel 3: HMMA flash attention, cp.async double-buffered.
// CTA = 128 q x full 4096 j, 8 warps; 64-j tiles, 2 SMEM buffers.
// ============================================================================
__global__ void __launch_bounds__(256, 1)
attn_kernel()
{
    extern __shared__ __align__(16) __nv_bfloat16 smem[];

    const int tid  = threadIdx.x;
    const int w    = tid >> 5;
    const int lane = tid & 31;
    const int g    = lane >> 2;       // row group 0..7
    const int t    = lane & 3;        // col group 0..3
    const int b    = blockIdx.y;
    const int q0   = blockIdx.x * TQ;
    const int row0 = q0 + w * 16 + g;

    const uint32_t sb = smem_u32(smem);

    // per-thread staging coordinates
    const int kr  = tid >> 2;          // K row 0..63
    const int ks_ = tid & 3;           // K 16B segment 0..3
    const __nv_bfloat16* kh_src0 = g_kh + ((size_t)b * NN + kr) * CQK + ks_ * 8;
    const __nv_bfloat16* kl_src0 = g_kl + ((size_t)b * NN + kr) * CQK + ks_ * 8;
    const uint32_t k_dst_h = (uint32_t)(kr * 80 + ks_ * 16);   // bytes in buffer
    const __nv_bfloat16* vh_src0 = g_vth + ((size_t)b * CH + tid) * NN;
    const __nv_bfloat16* vl_src0 = g_vtl + ((size_t)b * CH + tid) * NN;
    const uint32_t v_dst_row = (uint32_t)(tid * 144);

    // ---- Q A-fragments (persist) ----
    unsigned qh[2][4], ql[2][4];
    {
        const __nv_bfloat16* qhp = g_qh + (size_t)b * NN * CQK;
        const __nv_bfloat16* qlp = g_ql + (size_t)b * NN * CQK;
#pragma unroll
        for (int kq = 0; kq < 2; kq++) {
            int c0 = kq * 16 + t * 2;
            qh[kq][0] = *(const unsigned*)(qhp + (size_t)row0 * CQK + c0);
            qh[kq][1] = *(const unsigned*)(qhp + (size_t)(row0 + 8) * CQK + c0);
            qh[kq][2] = *(const unsigned*)(qhp + (size_t)row0 * CQK + c0 + 8);
            qh[kq][3] = *(const unsigned*)(qhp + (size_t)(row0 + 8) * CQK + c0 + 8);
            ql[kq][0] = *(const unsigned*)(qlp + (size_t)row0 * CQK + c0);
            ql[kq][1] = *(const unsigned*)(qlp + (size_t)(row0 + 8) * CQK + c0);
            ql[kq][2] = *(const unsigned*)(qlp + (size_t)row0 * CQK + c0 + 8);
            ql[kq][3] = *(const unsigned*)(qlp + (size_t)(row0 + 8) * CQK + c0 + 8);
        }
    }

    // persistent O accumulators
    float o[32][4];
#pragma unroll
    for (int cb = 0; cb < 32; cb++) {
        o[cb][0] = 0.f; o[cb][1] = 0.f; o[cb][2] = 0.f; o[cb][3] = 0.f;
    }
    float rs0 = 0.f, rs1 = 0.f;

    // ---- stage tile 0 into buffer 0 ----
    {
        uint32_t bb = sb;   // buffer 0
        cp16(bb + KH_B + k_dst_h, kh_src0);
        cp16(bb + KL_B + k_dst_h, kl_src0);
#pragma unroll
        for (int i = 0; i < 8; i++) {
            cp16(bb + VH_B + v_dst_row + i * 16, vh_src0 + i * 8);
            cp16(bb + VL_B + v_dst_row + i * 16, vl_src0 + i * 8);
        }
    }
    CP_COMMIT();

    for (int tl = 0; tl < NTILES; tl++) {
        // ---- stage tile tl+1 into the other buffer (overlaps compute) ----
        if (tl + 1 < NTILES) {
            const int j1 = (tl + 1) * TJ;
            uint32_t bb = sb + ((tl + 1) & 1) * BUFB;
            cp16(bb + KH_B + k_dst_h, kh_src0 + (size_t)j1 * CQK);
            cp16(bb + KL_B + k_dst_h, kl_src0 + (size_t)j1 * CQK);
#pragma unroll
            for (int i = 0; i < 8; i++) {
                cp16(bb + VH_B + v_dst_row + i * 16, vh_src0 + j1 + i * 8);
                cp16(bb + VL_B + v_dst_row + i * 16, vl_src0 + j1 + i * 8);
            }
        }
        CP_COMMIT();          // (possibly empty group — completes immediately)
        CP_WAIT1();           // tile tl resident
        __syncthreads();

        const __nv_bfloat16* ksh_h = smem + (tl & 1) * BUFE + KHe;
        const __nv_bfloat16* ksh_l = smem + (tl & 1) * BUFE + KLe;
        const __nv_bfloat16* vsh_h = smem + (tl & 1) * BUFE + VHe;
        const __nv_bfloat16* vsh_l = smem + (tl & 1) * BUFE + VLe;

#pragma unroll
        for (int kb = 0; kb < 4; kb++) {
            // ---- QK: two j-subblocks of 8 -> S fragments ----
            float s0[4] = {0.f, 0.f, 0.f, 0.f};
            float s1[4] = {0.f, 0.f, 0.f, 0.f};
#pragma unroll
            for (int jbi = 0; jbi < 2; jbi++) {
                int jb = kb * 2 + jbi;
                const __nv_bfloat16* krh = ksh_h + (jb * 8 + g) * KPAD;
                const __nv_bfloat16* krl = ksh_l + (jb * 8 + g) * KPAD;
                float* sd = jbi ? s1 : s0;
#pragma unroll
                for (int kq = 0; kq < 2; kq++) {
                    int c0 = kq * 16 + t * 2;
                    unsigned kh0 = *(const unsigned*)(krh + c0);
                    unsigned kh1 = *(const unsigned*)(krh + c0 + 8);
                    unsigned kl0 = *(const unsigned*)(krl + c0);
                    unsigned kl1 = *(const unsigned*)(krl + c0 + 8);
                    mma_bf16(sd, qh[kq], kh0, kh1);
                    mma_bf16(sd, qh[kq], kl0, kl1);
                    mma_bf16(sd, ql[kq], kh0, kh1);
                }
            }

            // ---- exp (no max-sub; fp32-safe) ----
            float e00 = __expf(s0[0]), e01 = __expf(s0[1]);
            float e02 = __expf(s0[2]), e03 = __expf(s0[3]);
            float e10 = __expf(s1[0]), e11 = __expf(s1[1]);
            float e12 = __expf(s1[2]), e13 = __expf(s1[3]);
            rs0 += e00 + e01 + e10 + e11;
            rs1 += e02 + e03 + e12 + e13;

            unsigned pa[4], pl[4];
            pa[0] = cvt_bf16x2(e01, e00);
            pa[1] = cvt_bf16x2(e03, e02);
            pa[2] = cvt_bf16x2(e11, e10);
            pa[3] = cvt_bf16x2(e13, e12);
            pl[0] = cvt_bf16x2(e01 - f_hi(pa[0]), e00 - f_lo(pa[0]));
            pl[1] = cvt_bf16x2(e03 - f_hi(pa[1]), e02 - f_lo(pa[1]));
            pl[2] = cvt_bf16x2(e11 - f_hi(pa[2]), e10 - f_lo(pa[2]));
            pl[3] = cvt_bf16x2(e13 - f_hi(pa[3]), e12 - f_lo(pa[3]));

            // ---- PV: O += Ph*Vh + Ph*Vl + Pl*Vh over 32 c-blocks ----
            const __nv_bfloat16* vbh = vsh_h + g * VPAD + kb * 16 + t * 2;
            const __nv_bfloat16* vbl = vsh_l + g * VPAD + kb * 16 + t * 2;
#pragma unroll
            for (int cb = 0; cb < 32; cb++) {
                unsigned vh0 = *(const unsigned*)(vbh + cb * 8 * VPAD);
                unsigned vh1 = *(const unsigned*)(vbh + cb * 8 * VPAD + 8);
                unsigned vl0 = *(const unsigned*)(vbl + cb * 8 * VPAD);
                unsigned vl1 = *(const unsigned*)(vbl + cb * 8 * VPAD + 8);
                mma_bf16(o[cb], pa, vh0, vh1);
                mma_bf16(o[cb], pa, vl0, vl1);
                mma_bf16(o[cb], pl, vh0, vh1);
            }
        }
        __syncthreads();   // compute done before next-next stage overwrites
    }

    // ---- rowsum reduce across the 4 lanes sharing a row ----
    rs0 += __shfl_xor_sync(0xffffffffu, rs0, 1);
    rs0 += __shfl_xor_sync(0xffffffffu, rs0, 2);
    rs1 += __shfl_xor_sync(0xffffffffu, rs1, 1);
    rs1 += __shfl_xor_sync(0xffffffffu, rs1, 2);
    const float inv0 = 1.0f / rs0;
    const float inv1 = 1.0f / rs1;

    float* d0p = g_ao + ((size_t)b * NN + row0) * CH;
    float* d1p = g_ao + ((size_t)b * NN + row0 + 8) * CH;
#pragma unroll
    for (int cb = 0; cb < 32; cb++) {
        *(float2*)(d0p + cb * 8 + t * 2) = make_float2(o[cb][0] * inv0, o[cb][1] * inv0);
        *(float2*)(d1p + cb * 8 + t * 2) = make_float2(o[cb][2] * inv1, o[cb][3] * inv1);
    }
}

// ============================================================================
// Kernel 4: output projection + residual.
// ============================================================================
__global__ void __launch_bounds__(256)
final_kernel(const float* __restrict__ x,
             const float* __restrict__ wg, const float* __restrict__ bg,
             float* __restrict__ y)
{
    __shared__ __align__(16) float as[CH * 36];
    const int b   = blockIdx.y;
    const int n0  = blockIdx.x * 32;
    const int tid = threadIdx.x;

    const float* aob = g_ao + ((size_t)b * NN + n0) * CH;
    for (int idx = tid; idx < 32 * CH; idx += 256) {
        int nn = idx >> 8, c = idx & 255;
        as[c * 36 + nn] = aob[(size_t)nn * CH + c];
    }
    __syncthreads();

    const int ng = tid & 7;
    const int cg = tid >> 3;

    float acc[8][4];
#pragma unroll
    for (int cc = 0; cc < 8; cc++) {
        float bb = bg[cg * 8 + cc];
#pragma unroll
        for (int i = 0; i < 4; i++) acc[cc][i] = bb;
    }

    for (int c4 = 0; c4 < CH; c4 += 4) {
        float xv[4][4];
#pragma unroll
        for (int i = 0; i < 4; i++)
            *(float4*)xv[i] = *(const float4*)(as + (c4 + i) * 36 + ng * 4);
#pragma unroll
        for (int cc = 0; cc < 8; cc++) {
            float wr[4];
            *(float4*)wr = *(const float4*)(wg + (size_t)(cg * 8 + cc) * CH + c4);
#pragma unroll
            for (int i = 0; i < 4; i++) {
                acc[cc][0] += wr[i] * xv[i][0];
                acc[cc][1] += wr[i] * xv[i][1];
                acc[cc][2] += wr[i] * xv[i][2];
                acc[cc][3] += wr[i] * xv[i][3];
            }
        }
    }

    const float* xb = x + (size_t)b * CH * NN + n0 + ng * 4;
    float*       yb = y + (size_t)b * CH * NN + n0 + ng * 4;
#pragma unroll
    for (int cc = 0; cc < 8; cc++) {
        int c = cg * 8 + cc;
        float4 xr = *(const float4*)(xb + (size_t)c * NN);
        *(float4*)(yb + (size_t)c * NN) =
            make_float4(xr.x + acc[cc][0], xr.y + acc[cc][1],
                        xr.z + acc[cc][2], xr.w + acc[cc][3]);
    }
}

// ============================================================================
extern "C" void kernel_launch(void* const* d_in, const int* in_sizes, int n_in,
                              void* d_out, int out_size)
{
    const float* x  = (const float*)d_in[0];
    const float* wq = (const float*)d_in[1];
    const float* bq = (const float*)d_in[2];
    const float* wk = (const float*)d_in[3];
    const float* bk = (const float*)d_in[4];
    const float* wv = (const float*)d_in[5];
    const float* bv = (const float*)d_in[6];
    const float* wg = (const float*)d_in[7];
    const float* bg = (const float*)d_in[8];
    float* y = (float*)d_out;

    const int attn_smem = SM_BF16_TOTAL * 2;   // bytes
    cudaFuncSetAttribute(attn_kernel,
                         cudaFuncAttributeMaxDynamicSharedMemorySize, attn_smem);

    proj_qk_kernel<<<dim3(NN / 32, BATCH), 256>>>(x, wq, bq, wk, bk);
    proj_v_kernel <<<dim3(NN / 32, BATCH), 256>>>(x, wv, bv);
    attn_kernel   <<<dim3(NN / TQ, BATCH), 256, attn_smem>>>();
    final_kernel  <<<dim3(NN / 32, BATCH), 256>>>(x, wg, bg, y);
}